// round 1
// baseline (speedup 1.0000x reference)
#include <cuda_runtime.h>
#include <cuda_bf16.h>
#include <math.h>
#include <stdint.h>

// ---------------- problem constants ----------------
#define BB 8
#define NN 64
#define IN_DIM 16
#define EDGE_DIM 8
#define DD 128
#define HH 4
#define DHH 32
#define LL 3
#define FF 512
#define MROWS (BB*NN*NN)          // 32768
static const float INV_SCALE = 0.17677669529663687f; // 1/sqrt(32)

// ---------------- scratch (device globals; no runtime alloc) ----------------
__device__ float g_tok[(size_t)MROWS*DD];
__device__ float g_q  [(size_t)MROWS*DD];
__device__ float g_k  [(size_t)MROWS*DD];
__device__ float g_v1 [(size_t)MROWS*DD];
__device__ float g_v2 [(size_t)MROWS*DD];
__device__ float g_o  [(size_t)MROWS*DD];
__device__ float g_tmp[(size_t)MROWS*DD];
__device__ float g_hid[(size_t)MROWS*FF];
__device__ float g_s  [(size_t)BB*HH*NN*NN*NN];   // [b][h][l][i][j]
__device__ int   g_mask_mode;                      // 0=int32, 1=uint8, 2=float32

// ---------------- mask dtype detector ----------------
// bool arrays may arrive as uint8 (bytes 0/1), int32 (le words 0/1) or float32
// (1.0f = 00 00 80 3F). Scan first 4096 bytes:
//   any byte == 0x3F            -> float32
//   any nonzero byte off %4!=0  -> uint8
//   else                        -> int32
__global__ void detect_mask_kernel(const unsigned char* __restrict__ m) {
    __shared__ int has3f, hasodd;
    if (threadIdx.x == 0) { has3f = 0; hasodd = 0; }
    __syncthreads();
    for (int i = threadIdx.x; i < 4096; i += blockDim.x) {
        unsigned char v = m[i];
        if (v == 0x3F) atomicOr(&has3f, 1);
        if (v != 0 && (i & 3)) atomicOr(&hasodd, 1);
    }
    __syncthreads();
    if (threadIdx.x == 0) g_mask_mode = has3f ? 2 : (hasodd ? 1 : 0);
}

// ---------------- embedding ----------------
__global__ void embed_kernel(const float* __restrict__ x,
                             const float* __restrict__ ea,
                             const void*  __restrict__ mask,
                             const float* __restrict__ nW, const float* __restrict__ nb,
                             const float* __restrict__ eW, const float* __restrict__ eb,
                             const float* __restrict__ noe) {
    int idx = blockIdx.x;                 // b*N*N + i*N + j
    int j = idx & 63;
    int i = (idx >> 6) & 63;
    int b = idx >> 12;
    int d = threadIdx.x;                  // 0..127
    __shared__ float sx[IN_DIM];
    __shared__ float se[EDGE_DIM];
    if (threadIdx.x < IN_DIM)  sx[threadIdx.x] = x[(b*NN + i)*IN_DIM + threadIdx.x];
    if (threadIdx.x < EDGE_DIM) se[threadIdx.x] = ea[((size_t)idx)*EDGE_DIM + threadIdx.x];
    __syncthreads();
    float v;
    if (i == j) {
        v = nb[d];
        #pragma unroll
        for (int e = 0; e < IN_DIM; e++) v = fmaf(sx[e], nW[e*DD + d], v);
    } else {
        bool m;
        int mm = g_mask_mode;
        if (mm == 0)      m = ((const int*)mask)[idx] != 0;
        else if (mm == 1) m = ((const unsigned char*)mask)[idx] != 0;
        else              m = ((const float*)mask)[idx] != 0.f;
        if (m) {
            v = eb[d];
            #pragma unroll
            for (int e = 0; e < EDGE_DIM; e++) v = fmaf(se[e], eW[e*DD + d], v);
        } else {
            v = noe[d];
        }
    }
    g_tok[(size_t)idx*DD + d] = v;
}

// ---------------- generic tiled SGEMM: C[M,N] = A[M,K] @ W[K,N] (+bias)(+res)(relu) ----
// BM=BN=64, BK=16, 256 threads, 4x4 microtile. M%64==0, N%64==0, K%16==0 required.
__global__ __launch_bounds__(256)
void gemm_kernel(const float* __restrict__ A, const float* __restrict__ W,
                 const float* __restrict__ bias, const float* __restrict__ res,
                 float* __restrict__ C, int M, int N, int K, int relu) {
    __shared__ float As[16][68];   // [k][m], padded
    __shared__ float Bs[16][64];   // [k][n]
    int bn = blockIdx.x * 64;
    int bm = blockIdx.y * 64;
    int t = threadIdx.x;
    int tn = t & 15, tm = t >> 4;
    float acc[4][4] = {};
    for (int k0 = 0; k0 < K; k0 += 16) {
        {   // A tile 64x16
            int r = t >> 2, kq = t & 3;
            float4 v = *(const float4*)(A + (size_t)(bm + r)*K + k0 + kq*4);
            As[kq*4+0][r] = v.x; As[kq*4+1][r] = v.y;
            As[kq*4+2][r] = v.z; As[kq*4+3][r] = v.w;
        }
        {   // W tile 16x64
            int r = t >> 4, nq = t & 15;
            *(float4*)&Bs[r][nq*4] = *(const float4*)(W + (size_t)(k0 + r)*N + bn + nq*4);
        }
        __syncthreads();
        #pragma unroll
        for (int k = 0; k < 16; k++) {
            float a[4], bb[4];
            #pragma unroll
            for (int u = 0; u < 4; u++) { a[u] = As[k][tm*4+u]; bb[u] = Bs[k][tn*4+u]; }
            #pragma unroll
            for (int i2 = 0; i2 < 4; i2++)
                #pragma unroll
                for (int j2 = 0; j2 < 4; j2++)
                    acc[i2][j2] = fmaf(a[i2], bb[j2], acc[i2][j2]);
        }
        __syncthreads();
    }
    #pragma unroll
    for (int i2 = 0; i2 < 4; i2++) {
        int m = bm + tm*4 + i2;
        size_t off = (size_t)m*N + bn + tn*4;
        float o0 = acc[i2][0], o1 = acc[i2][1], o2 = acc[i2][2], o3 = acc[i2][3];
        if (bias) {
            int nb0 = bn + tn*4;
            o0 += bias[nb0]; o1 += bias[nb0+1]; o2 += bias[nb0+2]; o3 += bias[nb0+3];
        }
        if (res) {
            float4 rr = *(const float4*)(res + off);
            o0 += rr.x; o1 += rr.y; o2 += rr.z; o3 += rr.w;
        }
        if (relu) {
            o0 = fmaxf(o0, 0.f); o1 = fmaxf(o1, 0.f);
            o2 = fmaxf(o2, 0.f); o3 = fmaxf(o3, 0.f);
        }
        *(float4*)(C + off) = make_float4(o0, o1, o2, o3);
    }
}

// ---------------- scores: s[b,h,l,i,j] = (1/SCALE) * q[b,i,l,h,:] . k[b,l,j,h,:] ------
__global__ __launch_bounds__(256)
void score_kernel() {
    int bid = blockIdx.x;                  // ((b*H+h)*64 + l)
    int l = bid & 63;
    int h = (bid >> 6) & 3;
    int b = bid >> 8;
    __shared__ float Qs[64][33];
    __shared__ float Ks[64][33];
    int t = threadIdx.x;
    for (int idx = t; idx < 64*32; idx += 256) {
        int r = idx >> 5, c = idx & 31;
        Qs[r][c] = g_q[((size_t)((b*NN + r)*NN + l) << 7) + h*DHH + c]; // r = i
        Ks[r][c] = g_k[((size_t)((b*NN + l)*NN + r) << 7) + h*DHH + c]; // r = j
    }
    __syncthreads();
    int tj = t & 15, ti = t >> 4;
    float acc[4][4] = {};
    #pragma unroll
    for (int c = 0; c < 32; c++) {
        float q[4], k[4];
        #pragma unroll
        for (int u = 0; u < 4; u++) { q[u] = Qs[ti*4+u][c]; k[u] = Ks[tj*4+u][c]; }
        #pragma unroll
        for (int i2 = 0; i2 < 4; i2++)
            #pragma unroll
            for (int j2 = 0; j2 < 4; j2++)
                acc[i2][j2] = fmaf(q[i2], k[j2], acc[i2][j2]);
    }
    float* dst = g_s + (size_t)bid * 4096;
    #pragma unroll
    for (int i2 = 0; i2 < 4; i2++)
        #pragma unroll
        for (int j2 = 0; j2 < 4; j2++)
            dst[(ti*4+i2)*64 + tj*4+j2] = acc[i2][j2] * INV_SCALE;
}

// ---------------- softmax over l, in place on g_s[b][h][l][i][j] ----------------
__global__ __launch_bounds__(64)
void softmax_kernel() {
    int bid = blockIdx.x;            // (b*H+h)*64 + i
    int i  = bid & 63;
    int bh = bid >> 6;
    int j  = threadIdx.x;
    size_t base = (size_t)bh * 262144 + (size_t)i*64 + j;
    float v[64];
    float mx = -1e30f;
    #pragma unroll
    for (int l = 0; l < 64; l++) { v[l] = g_s[base + (size_t)l*4096]; mx = fmaxf(mx, v[l]); }
    float s = 0.f;
    #pragma unroll
    for (int l = 0; l < 64; l++) { v[l] = __expf(v[l] - mx); s += v[l]; }
    float inv = 1.f / s;
    #pragma unroll
    for (int l = 0; l < 64; l++) g_s[base + (size_t)l*4096] = v[l] * inv;
}

// ---------------- o[b,i,j,h,d] = sum_l a[b,h,l,i,j]*v1[b,i,l,h,d]*v2[b,l,j,h,d] ------
__global__ __launch_bounds__(256)
void attn_o_kernel() {
    int h = blockIdx.x & 3;
    int i = (blockIdx.x >> 2) & 63;
    int b = blockIdx.x >> 8;
    __shared__ float v1s[64][36];    // [l][dd], padded for float4 alignment
    __shared__ float as[64][64];     // [l][j]
    int t = threadIdx.x;
    for (int idx = t; idx < 64*32; idx += 256) {
        int l = idx >> 5, c = idx & 31;
        v1s[l][c] = g_v1[((size_t)((b*NN + i)*NN + l) << 7) + h*DHH + c];
    }
    for (int idx = t; idx < 4096; idx += 256) {
        int l = idx >> 6, j = idx & 63;
        as[l][j] = g_s[(size_t)((b*HH + h)*NN + l)*4096 + i*64 + j];
    }
    __syncthreads();
    int td = t & 7;                  // d4 index -> d = h*32 + td*4 .. +3
    int tj = t >> 3;                 // 0..31
    int j0 = tj, j1 = tj + 32;
    float4 acc0 = {0,0,0,0}, acc1 = {0,0,0,0};
    #pragma unroll 4
    for (int l = 0; l < 64; l++) {
        float a0 = as[l][j0];
        float a1 = as[l][j1];
        float4 v1v = *(const float4*)&v1s[l][td*4];
        const float* base = g_v2 + ((size_t)(b*NN + l)*NN << 7) + h*DHH + td*4;
        float4 w0 = *(const float4*)(base + (size_t)j0*DD);
        float4 w1 = *(const float4*)(base + (size_t)j1*DD);
        acc0.x = fmaf(a0, v1v.x * w0.x, acc0.x);
        acc0.y = fmaf(a0, v1v.y * w0.y, acc0.y);
        acc0.z = fmaf(a0, v1v.z * w0.z, acc0.z);
        acc0.w = fmaf(a0, v1v.w * w0.w, acc0.w);
        acc1.x = fmaf(a1, v1v.x * w1.x, acc1.x);
        acc1.y = fmaf(a1, v1v.y * w1.y, acc1.y);
        acc1.z = fmaf(a1, v1v.z * w1.z, acc1.z);
        acc1.w = fmaf(a1, v1v.w * w1.w, acc1.w);
    }
    size_t o0 = ((size_t)((b*NN + i)*NN + j0) << 7) + h*DHH + td*4;
    size_t o1 = ((size_t)((b*NN + i)*NN + j1) << 7) + h*DHH + td*4;
    *(float4*)(g_o + o0) = acc0;
    *(float4*)(g_o + o1) = acc1;
}

// ---------------- layernorm over last dim (128) ----------------
__global__ __launch_bounds__(128)
void ln_kernel(const float* __restrict__ in, const float* __restrict__ gw,
               const float* __restrict__ bw, float* __restrict__ out) {
    int row = blockIdx.x, d = threadIdx.x;
    size_t off = (size_t)row*DD + d;
    float v = in[off];
    __shared__ float r1[4], r2[4];
    float s = v;
    #pragma unroll
    for (int o = 16; o > 0; o >>= 1) s += __shfl_xor_sync(0xffffffffu, s, o);
    if ((d & 31) == 0) r1[d >> 5] = s;
    __syncthreads();
    float mean = (r1[0] + r1[1] + r1[2] + r1[3]) * 0.0078125f;
    float c = v - mean;
    float s2 = c * c;
    #pragma unroll
    for (int o = 16; o > 0; o >>= 1) s2 += __shfl_xor_sync(0xffffffffu, s2, o);
    if ((d & 31) == 0) r2[d >> 5] = s2;
    __syncthreads();
    float var = (r2[0] + r2[1] + r2[2] + r2[3]) * 0.0078125f;
    out[off] = c * rsqrtf(var + 1e-5f) * gw[d] + bw[d];
}

// ---------------- final: out[b,n] = diag_tok . Wout + bout ----------------
__global__ __launch_bounds__(128)
void out_kernel(const float* __restrict__ Wout, const float* __restrict__ bout,
                float* __restrict__ out) {
    int bn = blockIdx.x;             // b*64 + n
    int n = bn & 63;
    int d = threadIdx.x;
    float v = g_tok[((size_t)bn*NN + n)*DD + d] * Wout[d];
    __shared__ float r[4];
    #pragma unroll
    for (int o = 16; o > 0; o >>= 1) v += __shfl_xor_sync(0xffffffffu, v, o);
    if ((d & 31) == 0) r[d >> 5] = v;
    __syncthreads();
    if (d == 0) out[bn] = r[0] + r[1] + r[2] + r[3] + bout[0];
}

// ---------------- host driver ----------------
extern "C" void kernel_launch(void* const* d_in, const int* in_sizes, int n_in,
                              void* d_out, int out_size) {
    const float* x    = (const float*)d_in[0];
    const float* ea   = (const float*)d_in[1];
    const void*  mask = d_in[2];
    const float* nW   = (const float*)d_in[3];
    const float* nb   = (const float*)d_in[4];
    const float* eW   = (const float*)d_in[5];
    const float* eb   = (const float*)d_in[6];
    const float* noe  = (const float*)d_in[7];
    const float* Wq   = (const float*)d_in[8];
    const float* Wk   = (const float*)d_in[9];
    const float* Wv1  = (const float*)d_in[10];
    const float* Wv2  = (const float*)d_in[11];
    const float* Wo   = (const float*)d_in[12];
    const float* bo   = (const float*)d_in[13];
    const float* ln1g = (const float*)d_in[14];
    const float* ln1b = (const float*)d_in[15];
    const float* W1   = (const float*)d_in[16];
    const float* b1   = (const float*)d_in[17];
    const float* W2   = (const float*)d_in[18];
    const float* b2   = (const float*)d_in[19];
    const float* ln2g = (const float*)d_in[20];
    const float* ln2b = (const float*)d_in[21];
    const float* Wout = (const float*)d_in[22];
    const float* bout = (const float*)d_in[23];

    float *tok, *q, *k, *v1, *v2, *o, *tmp, *hid;
    cudaGetSymbolAddress((void**)&tok, g_tok);
    cudaGetSymbolAddress((void**)&q,   g_q);
    cudaGetSymbolAddress((void**)&k,   g_k);
    cudaGetSymbolAddress((void**)&v1,  g_v1);
    cudaGetSymbolAddress((void**)&v2,  g_v2);
    cudaGetSymbolAddress((void**)&o,   g_o);
    cudaGetSymbolAddress((void**)&tmp, g_tmp);
    cudaGetSymbolAddress((void**)&hid, g_hid);

    detect_mask_kernel<<<1, 256>>>((const unsigned char*)mask);
    embed_kernel<<<MROWS, DD>>>(x, ea, mask, nW, nb, eW, eb, noe);

    dim3 g128(DD/64, MROWS/64);      // N=128 gemms
    dim3 g512(FF/64, MROWS/64);      // N=512 gemm

    for (int l = 0; l < LL; l++) {
        const float* Wq_l  = Wq  + (size_t)l*DD*DD;
        const float* Wk_l  = Wk  + (size_t)l*DD*DD;
        const float* Wv1_l = Wv1 + (size_t)l*DD*DD;
        const float* Wv2_l = Wv2 + (size_t)l*DD*DD;
        const float* Wo_l  = Wo  + (size_t)l*DD*DD;
        const float* bo_l  = bo  + (size_t)l*DD;
        const float* g1_l  = ln1g + (size_t)l*DD;
        const float* b1l_l = ln1b + (size_t)l*DD;
        const float* W1_l  = W1  + (size_t)l*DD*FF;
        const float* bf1_l = b1  + (size_t)l*FF;
        const float* W2_l  = W2  + (size_t)l*FF*DD;
        const float* bf2_l = b2  + (size_t)l*DD;
        const float* g2_l  = ln2g + (size_t)l*DD;
        const float* b2l_l = ln2b + (size_t)l*DD;

        gemm_kernel<<<g128, 256>>>(tok, Wq_l,  nullptr, nullptr, q,  MROWS, DD, DD, 0);
        gemm_kernel<<<g128, 256>>>(tok, Wk_l,  nullptr, nullptr, k,  MROWS, DD, DD, 0);
        gemm_kernel<<<g128, 256>>>(tok, Wv1_l, nullptr, nullptr, v1, MROWS, DD, DD, 0);
        gemm_kernel<<<g128, 256>>>(tok, Wv2_l, nullptr, nullptr, v2, MROWS, DD, DD, 0);

        score_kernel<<<BB*HH*NN, 256>>>();
        softmax_kernel<<<BB*HH*NN, 64>>>();
        attn_o_kernel<<<BB*NN*HH, 256>>>();

        gemm_kernel<<<g128, 256>>>(o, Wo_l, bo_l, tok, tmp, MROWS, DD, DD, 0);
        ln_kernel<<<MROWS, 128>>>(tmp, g1_l, b1l_l, tok);

        gemm_kernel<<<g512, 256>>>(tok, W1_l, bf1_l, nullptr, hid, MROWS, FF, DD, 1);
        gemm_kernel<<<g128, 256>>>(hid, W2_l, bf2_l, tok, tmp, MROWS, DD, FF, 0);
        ln_kernel<<<MROWS, 128>>>(tmp, g2_l, b2l_l, tok);
    }

    out_kernel<<<BB*NN, 128>>>(Wout, bout, (float*)d_out);
}